// round 2
// baseline (speedup 1.0000x reference)
#include <cuda_runtime.h>
#include <math.h>

// Problem constants
#define B_   256
#define S_   200
#define NQ_  400
#define K_   4
#define M_   50
#define KD_  50
#define VD_  200
#define FD_  50
#define NQT  (NQ_ + 1)        // 401 q values
#define NROW (NQT * K_)       // 1604 (q,r) rows

// ---------------- Precomputed tables (device scratch) ----------------
__device__ float g_corr_tab[NQT * M_];     // softmax(tanh(qemb@Wqk)@key^T)
__device__ float g_sumq_tab[NQT * FD_];    // qemb @ W_sum[200:250] + b_sum
__device__ float g_beta_tab[NQT * 3];      // tanh(qemb@W_th + b_th)
__device__ float g_dq_tab[NQT];            // qemb @ W_disc[50:100] + b_disc
__device__ float g_e_tab[NROW * VD_];      // sigmoid(VE(q,r) @ W_e + b_e)
__device__ float g_a_tab[NROW * VD_];      // tanh   (VE(q,r) @ W_a + b_a)

// ---------------- Kernel 1: q-indexed tables -------------------------
__global__ void qtab_kernel(const float* __restrict__ q_tab,
                            const float* __restrict__ key_mem,
                            const float* __restrict__ W_qk,
                            const float* __restrict__ b_qk,
                            const float* __restrict__ W_sum,
                            const float* __restrict__ b_sum,
                            const float* __restrict__ W_th,
                            const float* __restrict__ b_th,
                            const float* __restrict__ W_disc,
                            const float* __restrict__ b_disc)
{
    int q = blockIdx.x;
    int t = threadIdx.x;
    __shared__ float qe[KD_];
    __shared__ float qk[KD_];
    __shared__ float lg[M_];
    __shared__ float red[2];

    if (t < KD_) qe[t] = q_tab[q * KD_ + t];
    __syncthreads();

    if (t < KD_) {
        // query_key = tanh(qemb @ W_qk + b_qk)
        float acc = b_qk[t];
        #pragma unroll 10
        for (int d = 0; d < KD_; d++) acc = fmaf(qe[d], W_qk[d * KD_ + t], acc);
        qk[t] = tanhf(acc);
        // sumq = qemb @ W_sum[200..249] + b_sum
        float s = b_sum[t];
        #pragma unroll 10
        for (int d = 0; d < KD_; d++) s = fmaf(qe[d], W_sum[(VD_ + d) * FD_ + t], s);
        g_sumq_tab[q * FD_ + t] = s;
    }
    if (t < 3) {
        float acc = b_th[t];
        for (int d = 0; d < KD_; d++) acc = fmaf(qe[d], W_th[d * 3 + t], acc);
        g_beta_tab[q * 3 + t] = tanhf(acc);
    }
    if (t == 63) {
        float acc = b_disc[0];
        for (int d = 0; d < KD_; d++) acc = fmaf(qe[d], W_disc[KD_ + d], acc);
        g_dq_tab[q] = acc;
    }
    __syncthreads();

    if (t < M_) {
        float acc = 0.f;
        #pragma unroll 10
        for (int d = 0; d < KD_; d++) acc = fmaf(qk[d], key_mem[t * KD_ + d], acc);
        lg[t] = acc;
    }
    __syncthreads();
    if (t == 0) {
        float mx = -1e30f;
        for (int m = 0; m < M_; m++) mx = fmaxf(mx, lg[m]);
        red[0] = mx;
    }
    __syncthreads();
    if (t < M_) lg[t] = expf(lg[t] - red[0]);
    __syncthreads();
    if (t == 0) {
        float s = 0.f;
        for (int m = 0; m < M_; m++) s += lg[m];
        red[1] = 1.f / s;
    }
    __syncthreads();
    if (t < M_) g_corr_tab[q * M_ + t] = lg[t] * red[1];
}

// ---------------- Kernel 2: erase/add tables over 1604 rows ----------
#define EA_ROWS 16
__global__ void ea_kernel(const float* __restrict__ W_v3,
                          const float* __restrict__ b_v,
                          const float* __restrict__ W_e,
                          const float* __restrict__ b_e,
                          const float* __restrict__ W_a,
                          const float* __restrict__ b_a)
{
    __shared__ float ve[EA_ROWS][VD_];
    int t = threadIdx.x;
    int row0 = blockIdx.x * EA_ROWS;

    // build value_emb for EA_ROWS (q,r) pairs
    for (int i = t; i < EA_ROWS * VD_; i += blockDim.x) {
        int rr = i / VD_;
        int d  = i - rr * VD_;
        int row = row0 + rr;
        if (row < NROW) {
            int q = row >> 2;
            int r = row & 3;
            float val = b_v[d];
            if (q > 0) {
                int idx = q - 1;   // clip(q-1, 0, 399)
                #pragma unroll
                for (int k = 0; k < K_; k++) {
                    int dd = (k > r) ? (k - r) : (r - k);
                    float wc = 1.0f - (float)dd / 3.0f;
                    if (wc > 0.0f)
                        val = fmaf(wc, W_v3[(k * NQ_ + idx) * VD_ + d], val);
                }
            }
            ve[rr][d] = val;
        }
    }
    __syncthreads();

    if (t < VD_) {
        int v = t;
        float acce[EA_ROWS], acca[EA_ROWS];
        #pragma unroll
        for (int rr = 0; rr < EA_ROWS; rr++) { acce[rr] = 0.f; acca[rr] = 0.f; }
        for (int d = 0; d < VD_; d++) {
            float we = W_e[d * VD_ + v];
            float wa = W_a[d * VD_ + v];
            #pragma unroll
            for (int rr = 0; rr < EA_ROWS; rr++) {
                float x = ve[rr][d];
                acce[rr] = fmaf(x, we, acce[rr]);
                acca[rr] = fmaf(x, wa, acca[rr]);
            }
        }
        float bev = b_e[v], bav = b_a[v];
        #pragma unroll
        for (int rr = 0; rr < EA_ROWS; rr++) {
            int row = row0 + rr;
            if (row < NROW) {
                g_e_tab[row * VD_ + v] = 1.0f / (1.0f + expf(-(acce[rr] + bev)));
                g_a_tab[row * VD_ + v] = tanhf(acca[rr] + bav);
            }
        }
    }
}

// ---------------- Kernel 3: sequential scan, one CTA per batch -------
__device__ __forceinline__ float softplusf(float x) {
    return (x > 20.0f) ? x : log1pf(expf(x));
}

__global__ __launch_bounds__(256, 2)
void scan_kernel(const int* __restrict__ q_data,
                 const int* __restrict__ r_data,
                 const float* __restrict__ init_mem,
                 const float* __restrict__ W_sum,
                 const float* __restrict__ W_ab,
                 const float* __restrict__ b_ab,
                 const float* __restrict__ W_disc,
                 float* __restrict__ out)
{
    int b = blockIdx.x;
    int t = threadIdx.x;
    int v = t;  // column ownership for t < 200

    __shared__ float Wsum_s[VD_ * FD_];   // 40 KB: rows 0..199 of W_sum
    __shared__ float Wab_s[64];
    __shared__ float Wdisc_s[64];
    __shared__ float w_sm[64];
    __shared__ float read_sm[VD_];
    __shared__ float part_sm[VD_];
    __shared__ int   q_row[S_];
    __shared__ int   r_row[S_];

    for (int i = t; i < VD_ * FD_; i += 256) Wsum_s[i] = W_sum[i];
    if (t < FD_) { Wab_s[t] = W_ab[t]; Wdisc_s[t] = W_disc[t]; }

    const int base = b * S_;
    if (t < S_) {
        q_row[t] = q_data[base + t];
        r_row[t] = r_data[base + t];
    }

    float memv[M_];
    if (t < VD_) {
        #pragma unroll
        for (int m = 0; m < M_; m++) memv[m] = init_mem[m * VD_ + v];
    }
    float b_ab0 = b_ab[0];
    __syncthreads();

    for (int s = 0; s < S_; s++) {
        int q = q_row[s];
        int r = r_row[s];
        if (t < M_) w_sm[t] = g_corr_tab[q * M_ + t];
        __syncthreads();                                   // sync A

        if (t < VD_) {
            const float* et = &g_e_tab[(q * 4 + r) * VD_];
            const float* at = &g_a_tab[(q * 4 + r) * VD_];
            float e_v = et[v];
            float a_v = at[v];
            float rd = 0.f;
            #pragma unroll
            for (int m = 0; m < M_; m++) {
                float old = memv[m];
                float wm  = w_sm[m];
                rd = fmaf(wm, old, rd);
                float tmp = fmaf(-old, e_v, a_v);          // a - old*e
                memv[m] = fmaf(wm, tmp, old);              // old + w*(a - old*e)
            }
            read_sm[v] = rd;
        }
        __syncthreads();                                   // sync B

        // partial summary: 4 quarters x 50 features
        if (t < VD_) {
            int f = t % FD_;
            int quarter = t / FD_;
            const float* Wp = &Wsum_s[(quarter * FD_) * FD_ + f];
            const float* rp = &read_sm[quarter * FD_];
            float acc = 0.f;
            #pragma unroll
            for (int i = 0; i < FD_; i++) acc = fmaf(rp[i], Wp[i * FD_], acc);
            part_sm[t] = acc;
        }
        __syncthreads();                                   // sync C

        if (t < 32) {
            float th_p, al_p;
            {
                float Sf = part_sm[t] + part_sm[t + 50] + part_sm[t + 100] +
                           part_sm[t + 150] + g_sumq_tab[q * FD_ + t];
                float sf = tanhf(Sf);
                th_p = sf * Wab_s[t];
                al_p = sf * Wdisc_s[t];
            }
            int f2 = t + 32;
            if (f2 < FD_) {
                float Sf = part_sm[f2] + part_sm[f2 + 50] + part_sm[f2 + 100] +
                           part_sm[f2 + 150] + g_sumq_tab[q * FD_ + f2];
                float sf = tanhf(Sf);
                th_p = fmaf(sf, Wab_s[f2], th_p);
                al_p = fmaf(sf, Wdisc_s[f2], al_p);
            }
            #pragma unroll
            for (int o = 16; o > 0; o >>= 1) {
                th_p += __shfl_down_sync(0xffffffffu, th_p, o);
                al_p += __shfl_down_sync(0xffffffffu, al_p, o);
            }
            if (t == 0) {
                float theta = 3.0f * (th_p + b_ab0);
                float alpha = softplusf(al_p + g_dq_tab[q]);
                float be0 = g_beta_tab[q * 3 + 0];
                float be1 = g_beta_tab[q * 3 + 1];
                float be2 = g_beta_tab[q * 3 + 2];
                float d0 = theta - be0;
                float d1 = theta - be1;
                float d2 = theta - be2;
                float c0 = alpha * d0;
                float c1 = alpha * (d0 + d1);
                float c2 = alpha * (d0 + d1 + d2);
                float mx = fmaxf(0.0f, fmaxf(c0, fmaxf(c1, c2)));
                float e0 = expf(0.0f - mx);
                float e1 = expf(c0 - mx);
                float e2 = expf(c1 - mx);
                float e3 = expf(c2 - mx);
                float inv = 1.0f / (e0 + e1 + e2 + e3);
                float4 p = make_float4(e0 * inv, e1 * inv, e2 * inv, e3 * inv);
                reinterpret_cast<float4*>(out)[base + s] = p;
            }
        }
        // no extra barrier needed: next writes to w_sm precede sync A;
        // part_sm/read_sm rewritten only after all threads pass syncs A/B.
    }
}

// ---------------- launch ---------------------------------------------
extern "C" void kernel_launch(void* const* d_in, const int* in_sizes, int n_in,
                              void* d_out, int out_size)
{
    const int*   q_data   = (const int*)  d_in[0];
    const int*   r_data   = (const int*)  d_in[1];
    const float* q_tab    = (const float*)d_in[2];
    const float* key_mem  = (const float*)d_in[3];
    const float* init_mem = (const float*)d_in[4];
    const float* W_qk     = (const float*)d_in[5];
    const float* b_qk     = (const float*)d_in[6];
    const float* W_v3     = (const float*)d_in[7];
    const float* b_v      = (const float*)d_in[8];
    const float* W_e      = (const float*)d_in[9];
    const float* b_e      = (const float*)d_in[10];
    const float* W_a      = (const float*)d_in[11];
    const float* b_a      = (const float*)d_in[12];
    const float* W_sum    = (const float*)d_in[13];
    const float* b_sum    = (const float*)d_in[14];
    const float* W_ab     = (const float*)d_in[15];
    const float* b_ab     = (const float*)d_in[16];
    const float* W_th     = (const float*)d_in[17];
    const float* b_th     = (const float*)d_in[18];
    const float* W_disc   = (const float*)d_in[19];
    const float* b_disc   = (const float*)d_in[20];
    float* out = (float*)d_out;

    qtab_kernel<<<NQT, 64>>>(q_tab, key_mem, W_qk, b_qk, W_sum, b_sum,
                             W_th, b_th, W_disc, b_disc);
    ea_kernel<<<(NROW + EA_ROWS - 1) / EA_ROWS, 256>>>(W_v3, b_v, W_e, b_e, W_a, b_a);
    scan_kernel<<<B_, 256>>>(q_data, r_data, init_mem, W_sum, W_ab, b_ab,
                             W_disc, out);
}

// round 3
// speedup vs baseline: 1.3202x; 1.3202x over previous
#include <cuda_runtime.h>
#include <math.h>

// Problem constants
#define B_   256
#define S_   200
#define NQ_  400
#define K_   4
#define M_   50
#define KD_  50
#define VD_  200
#define FD_  50
#define NQT  (NQ_ + 1)        // 401 q values
#define NROW (NQT * K_)       // 1604 (q,r) rows

// ---------------- Precomputed tables (device scratch) ----------------
__device__ float g_corr_tab[NQT * M_];       // softmax(tanh(qemb@Wqk)@key^T)
__device__ float g_sumq_tab[NQT * FD_];      // qemb @ W_sum[200:250] + b_sum
__device__ float g_beta_tab[NQT * 4];        // tanh(qemb@W_th + b_th) (padded)
__device__ float g_dq_tab[NQT];              // qemb @ W_disc[50:100] + b_disc
__device__ float g_ea_tab[NROW * VD_ * 2];   // interleaved (erase, add) per (q,r) row

// ---------------- Kernel 1: q-indexed tables -------------------------
__global__ void qtab_kernel(const float* __restrict__ q_tab,
                            const float* __restrict__ key_mem,
                            const float* __restrict__ W_qk,
                            const float* __restrict__ b_qk,
                            const float* __restrict__ W_sum,
                            const float* __restrict__ b_sum,
                            const float* __restrict__ W_th,
                            const float* __restrict__ b_th,
                            const float* __restrict__ W_disc,
                            const float* __restrict__ b_disc)
{
    int q = blockIdx.x;
    int t = threadIdx.x;
    __shared__ float qe[KD_];
    __shared__ float qk[KD_];
    __shared__ float lg[M_];
    __shared__ float red[2];

    if (t < KD_) qe[t] = q_tab[q * KD_ + t];
    __syncthreads();

    if (t < KD_) {
        float acc = b_qk[t];
        #pragma unroll 10
        for (int d = 0; d < KD_; d++) acc = fmaf(qe[d], W_qk[d * KD_ + t], acc);
        qk[t] = tanhf(acc);
        float s = b_sum[t];
        #pragma unroll 10
        for (int d = 0; d < KD_; d++) s = fmaf(qe[d], W_sum[(VD_ + d) * FD_ + t], s);
        g_sumq_tab[q * FD_ + t] = s;
    }
    if (t < 3) {
        float acc = b_th[t];
        for (int d = 0; d < KD_; d++) acc = fmaf(qe[d], W_th[d * 3 + t], acc);
        g_beta_tab[q * 4 + t] = tanhf(acc);
    }
    if (t == 63) {
        float acc = b_disc[0];
        for (int d = 0; d < KD_; d++) acc = fmaf(qe[d], W_disc[KD_ + d], acc);
        g_dq_tab[q] = acc;
    }
    __syncthreads();

    if (t < M_) {
        float acc = 0.f;
        #pragma unroll 10
        for (int d = 0; d < KD_; d++) acc = fmaf(qk[d], key_mem[t * KD_ + d], acc);
        lg[t] = acc;
    }
    __syncthreads();
    if (t == 0) {
        float mx = -1e30f;
        for (int m = 0; m < M_; m++) mx = fmaxf(mx, lg[m]);
        red[0] = mx;
    }
    __syncthreads();
    if (t < M_) lg[t] = expf(lg[t] - red[0]);
    __syncthreads();
    if (t == 0) {
        float s = 0.f;
        for (int m = 0; m < M_; m++) s += lg[m];
        red[1] = 1.f / s;
    }
    __syncthreads();
    if (t < M_) g_corr_tab[q * M_ + t] = lg[t] * red[1];
}

// ---------------- Kernel 2: erase/add tables over 1604 rows ----------
#define EA_ROWS 16
__global__ void ea_kernel(const float* __restrict__ W_v3,
                          const float* __restrict__ b_v,
                          const float* __restrict__ W_e,
                          const float* __restrict__ b_e,
                          const float* __restrict__ W_a,
                          const float* __restrict__ b_a)
{
    __shared__ float ve[EA_ROWS][VD_];
    int t = threadIdx.x;
    int row0 = blockIdx.x * EA_ROWS;

    for (int i = t; i < EA_ROWS * VD_; i += blockDim.x) {
        int rr = i / VD_;
        int d  = i - rr * VD_;
        int row = row0 + rr;
        if (row < NROW) {
            int q = row >> 2;
            int r = row & 3;
            float val = b_v[d];
            if (q > 0) {
                int idx = q - 1;
                #pragma unroll
                for (int k = 0; k < K_; k++) {
                    int dd = (k > r) ? (k - r) : (r - k);
                    float wc = 1.0f - (float)dd / 3.0f;
                    if (wc > 0.0f)
                        val = fmaf(wc, W_v3[(k * NQ_ + idx) * VD_ + d], val);
                }
            }
            ve[rr][d] = val;
        }
    }
    __syncthreads();

    if (t < VD_) {
        int v = t;
        float acce[EA_ROWS], acca[EA_ROWS];
        #pragma unroll
        for (int rr = 0; rr < EA_ROWS; rr++) { acce[rr] = 0.f; acca[rr] = 0.f; }
        for (int d = 0; d < VD_; d++) {
            float we = W_e[d * VD_ + v];
            float wa = W_a[d * VD_ + v];
            #pragma unroll
            for (int rr = 0; rr < EA_ROWS; rr++) {
                float x = ve[rr][d];
                acce[rr] = fmaf(x, we, acce[rr]);
                acca[rr] = fmaf(x, wa, acca[rr]);
            }
        }
        float bev = b_e[v], bav = b_a[v];
        #pragma unroll
        for (int rr = 0; rr < EA_ROWS; rr++) {
            int row = row0 + rr;
            if (row < NROW) {
                float2 ea;
                ea.x = 1.0f / (1.0f + expf(-(acce[rr] + bev)));   // erase
                ea.y = tanhf(acca[rr] + bav);                     // add
                *reinterpret_cast<float2*>(&g_ea_tab[(row * VD_ + v) * 2]) = ea;
            }
        }
    }
}

// ---------------- Kernel 3: pipelined sequential scan ----------------
__device__ __forceinline__ float softplusf(float x) {
    return (x > 20.0f) ? x : log1pf(expf(x));
}

__global__ __launch_bounds__(256, 2)
void scan_kernel(const int* __restrict__ q_data,
                 const int* __restrict__ r_data,
                 const float* __restrict__ init_mem,
                 const float* __restrict__ W_sum,
                 const float* __restrict__ W_ab,
                 const float* __restrict__ b_ab,
                 const float* __restrict__ W_disc,
                 float* __restrict__ out)
{
    int b = blockIdx.x;
    int t = threadIdx.x;
    int v = t;                 // column ownership for t < 200
    int f = t % FD_;
    int quarter = t / FD_;

    __shared__ float w_sm[2][52];       // double-buffered correlation weights
    __shared__ float read_sm[VD_];
    __shared__ float part_sm[VD_];
    __shared__ int   q_row[S_];
    __shared__ int   r_row[S_];

    const int base = b * S_;
    for (int i = t; i < S_; i += 256) {
        q_row[i] = q_data[base + i];
        r_row[i] = r_data[base + i];
    }

    float memv[M_];
    float Wreg[FD_];
    if (t < VD_) {
        #pragma unroll
        for (int m = 0; m < M_; m++) memv[m] = init_mem[m * VD_ + v];
        #pragma unroll
        for (int i = 0; i < FD_; i++) Wreg[i] = W_sum[(quarter * FD_ + i) * FD_ + f];
    }

    // warp 7 (t in [224,256)) = epilogue warp: constants
    int l = t - 224;
    float wab1 = 0.f, wab2 = 0.f, wd1 = 0.f, wd2 = 0.f, b_ab0 = 0.f;
    if (t >= 224) {
        wab1 = W_ab[l];  wd1 = W_disc[l];
        if (l + 32 < FD_) { wab2 = W_ab[l + 32]; wd2 = W_disc[l + 32]; }
        b_ab0 = b_ab[0];
    }
    __syncthreads();   // q_row/r_row ready

    // Prologue: prefetch step-0 operands
    float2 ea_cur = make_float2(0.f, 0.f), ea_nxt;
    {
        int q0 = q_row[0], r0 = r_row[0];
        if (t < VD_)
            ea_cur = __ldg(reinterpret_cast<const float2*>(
                         &g_ea_tab[((q0 * 4 + r0) * VD_ + v) * 2]));
        if (t >= 224) {
            for (int m = l; m < M_; m += 32)
                w_sm[0][m] = g_corr_tab[q0 * M_ + m];
        }
    }
    __syncthreads();

    for (int s = 0; s < S_; s++) {
        int cur = s & 1, nxt = cur ^ 1;
        int q = q_row[s];
        int sn = (s + 1 < S_) ? s + 1 : s;
        int qn = q_row[sn], rn = r_row[sn];

        // ---- prefetch: next-step tables + this-step epilogue operands ----
        if (t < VD_)
            ea_nxt = __ldg(reinterpret_cast<const float2*>(
                         &g_ea_tab[((qn * 4 + rn) * VD_ + v) * 2]));
        float sq1 = 0.f, sq2 = 0.f, be0 = 0.f, be1 = 0.f, be2 = 0.f, dq = 0.f;
        if (t >= 224) {
            for (int m = l; m < M_; m += 32)
                w_sm[nxt][m] = g_corr_tab[qn * M_ + m];
            sq1 = __ldg(&g_sumq_tab[q * FD_ + l]);
            if (l + 32 < FD_) sq2 = __ldg(&g_sumq_tab[q * FD_ + l + 32]);
            if (l == 0) {
                be0 = g_beta_tab[q * 4 + 0];
                be1 = g_beta_tab[q * 4 + 1];
                be2 = g_beta_tab[q * 4 + 2];
                dq  = g_dq_tab[q];
            }
        }

        // ---- memory read + update (register-resident state) ----
        if (t < VD_) {
            float e_v = ea_cur.x, a_v = ea_cur.y;
            float rd0 = 0.f, rd1 = 0.f;
            #pragma unroll
            for (int m = 0; m < M_; m += 2) {
                float w0 = w_sm[cur][m],   w1 = w_sm[cur][m + 1];
                float o0 = memv[m],        o1 = memv[m + 1];
                rd0 = fmaf(w0, o0, rd0);
                rd1 = fmaf(w1, o1, rd1);
                memv[m]     = fmaf(w0, fmaf(-o0, e_v, a_v), o0);
                memv[m + 1] = fmaf(w1, fmaf(-o1, e_v, a_v), o1);
            }
            read_sm[v] = rd0 + rd1;
        }
        __syncthreads();                                   // sync B

        // ---- partial summary: W_sum register-resident, reads broadcast ----
        if (t < VD_) {
            const float* rp = &read_sm[quarter * FD_];
            float a0 = 0.f, a1 = 0.f;
            #pragma unroll
            for (int i = 0; i < FD_; i += 2) {
                a0 = fmaf(rp[i],     Wreg[i],     a0);
                a1 = fmaf(rp[i + 1], Wreg[i + 1], a1);
            }
            part_sm[t] = a0 + a1;
        }
        __syncthreads();                                   // sync C

        // ---- epilogue on dedicated warp 7 (overlaps next step's update) ----
        if (t >= 224) {
            float th_p, al_p;
            {
                float Sf = part_sm[l] + part_sm[l + 50] + part_sm[l + 100] +
                           part_sm[l + 150] + sq1;
                float sf = tanhf(Sf);
                th_p = sf * wab1;
                al_p = sf * wd1;
            }
            if (l + 32 < FD_) {
                int f2 = l + 32;
                float Sf = part_sm[f2] + part_sm[f2 + 50] + part_sm[f2 + 100] +
                           part_sm[f2 + 150] + sq2;
                float sf = tanhf(Sf);
                th_p = fmaf(sf, wab2, th_p);
                al_p = fmaf(sf, wd2, al_p);
            }
            #pragma unroll
            for (int o = 16; o > 0; o >>= 1) {
                th_p += __shfl_down_sync(0xffffffffu, th_p, o);
                al_p += __shfl_down_sync(0xffffffffu, al_p, o);
            }
            if (l == 0) {
                float theta = 3.0f * (th_p + b_ab0);
                float alpha = softplusf(al_p + dq);
                float d0 = theta - be0;
                float d1 = theta - be1;
                float d2 = theta - be2;
                float c0 = alpha * d0;
                float c1 = alpha * (d0 + d1);
                float c2 = alpha * (d0 + d1 + d2);
                float mx = fmaxf(0.0f, fmaxf(c0, fmaxf(c1, c2)));
                float e0 = expf(0.0f - mx);
                float e1 = expf(c0 - mx);
                float e2 = expf(c1 - mx);
                float e3 = expf(c2 - mx);
                float inv = 1.0f / (e0 + e1 + e2 + e3);
                float4 p = make_float4(e0 * inv, e1 * inv, e2 * inv, e3 * inv);
                reinterpret_cast<float4*>(out)[base + s] = p;
            }
        }
        ea_cur = ea_nxt;
        // No end barrier needed: w_sm[nxt] writes (issued before sync B, drained
        // there) are read only after sync C; read_sm/part_sm rewrites at s+1 are
        // separated from s readers by sync C(s) / sync B(s+1) respectively.
    }
}

// ---------------- launch ---------------------------------------------
extern "C" void kernel_launch(void* const* d_in, const int* in_sizes, int n_in,
                              void* d_out, int out_size)
{
    const int*   q_data   = (const int*)  d_in[0];
    const int*   r_data   = (const int*)  d_in[1];
    const float* q_tab    = (const float*)d_in[2];
    const float* key_mem  = (const float*)d_in[3];
    const float* init_mem = (const float*)d_in[4];
    const float* W_qk     = (const float*)d_in[5];
    const float* b_qk     = (const float*)d_in[6];
    const float* W_v3     = (const float*)d_in[7];
    const float* b_v      = (const float*)d_in[8];
    const float* W_e      = (const float*)d_in[9];
    const float* b_e      = (const float*)d_in[10];
    const float* W_a      = (const float*)d_in[11];
    const float* b_a      = (const float*)d_in[12];
    const float* W_sum    = (const float*)d_in[13];
    const float* b_sum    = (const float*)d_in[14];
    const float* W_ab     = (const float*)d_in[15];
    const float* b_ab     = (const float*)d_in[16];
    const float* W_th     = (const float*)d_in[17];
    const float* b_th     = (const float*)d_in[18];
    const float* W_disc   = (const float*)d_in[19];
    const float* b_disc   = (const float*)d_in[20];
    float* out = (float*)d_out;

    qtab_kernel<<<NQT, 64>>>(q_tab, key_mem, W_qk, b_qk, W_sum, b_sum,
                             W_th, b_th, W_disc, b_disc);
    ea_kernel<<<(NROW + EA_ROWS - 1) / EA_ROWS, 256>>>(W_v3, b_v, W_e, b_e, W_a, b_a);
    scan_kernel<<<B_, 256>>>(q_data, r_data, init_mem, W_sum, W_ab, b_ab,
                             W_disc, out);
}